// round 10
// baseline (speedup 1.0000x reference)
#include <cuda_runtime.h>

#define N_SPH 128
#define PPB   2048         // points per block (8 per thread)
#define CAP   640          // per-block compaction capacity (overflow -> slow path)
typedef unsigned long long u64;

// -ln(1e-6)/32 : exact output when s clamps at 1e-6
#define FASTVAL 0.4317347049363836f

// ---- packed f32x2 helpers (sm_100+) ----
__device__ __forceinline__ u64 pk2(float lo, float hi) {
    u64 r; asm("mov.b64 %0, {%1, %2};" : "=l"(r) : "f"(lo), "f"(hi)); return r;
}
__device__ __forceinline__ float2 up2(u64 v) {
    float2 f; asm("mov.b64 {%0, %1}, %2;" : "=f"(f.x), "=f"(f.y) : "l"(v)); return f;
}
__device__ __forceinline__ u64 f2fma(u64 a, u64 b, u64 c) {
    u64 d; asm("fma.rn.f32x2 %0, %1, %2, %3;" : "=l"(d) : "l"(a), "l"(b), "l"(c)); return d;
}
__device__ __forceinline__ u64 f2mul(u64 a, u64 b) {
    u64 d; asm("mul.rn.f32x2 %0, %1, %2;" : "=l"(d) : "l"(a), "l"(b)); return d;
}
__device__ __forceinline__ float sqrt_ap(float x) {
    float r; asm("sqrt.approx.f32 %0, %1;" : "=f"(r) : "f"(x)); return r;
}
__device__ __forceinline__ float ex2_ap(float x) {
    float r; asm("ex2.approx.f32 %0, %1;" : "=f"(r) : "f"(x)); return r;
}
__device__ __forceinline__ float lg2_ap(float x) {
    float r; asm("lg2.approx.f32 %0, %1;" : "=f"(r) : "f"(x)); return r;
}

__global__ void __launch_bounds__(256, 4) smoothed_fused(
    const float* __restrict__ p,
    const float* __restrict__ centers,
    const float* __restrict__ radii,
    const float* __restrict__ tfs,
    float* __restrict__ out, int npts) {

    __shared__ __align__(16) float  shc[N_SPH * 28];   // 14336 B packed consts
    __shared__ __align__(16) float4 sbuf[CAP];         // 10240 B compacted points
    __shared__ float  spart[8 * (CAP + 1)];            // 20512 B group partials
    __shared__ int s_thr2_bits;
    __shared__ int s_count;

    const int tid = threadIdx.x;
    if (tid == 0) { s_thr2_bits = 0; s_count = 0; }

    // ---- prefetch this thread's 8 points (6 float4 loads) ----
    int base = blockIdx.x * PPB + tid * 8;
    float4 f[6];
    bool inb = base + 7 < npts;          // npts % PPB == 0 in this problem
    if (inb) {
        const float4* p4 = reinterpret_cast<const float4*>(p);
        long fb = (long)(blockIdx.x * (PPB / 4) * 3) + tid * 6;
        #pragma unroll
        for (int i = 0; i < 6; ++i) f[i] = p4[fb + i];
    }
    __syncthreads();

    // ---- phase A: threads 0..127 build sphere consts + radial threshold ----
    if (tid < N_SPH) {
        int i = tid;
        float T[3][3];
        #pragma unroll
        for (int r = 0; r < 3; ++r)
            #pragma unroll
            for (int c = 0; c < 3; ++c)
                T[r][c] = tfs[i * 9 + r * 3 + c] + ((r == c) ? 1.0f : 0.0f);
        float cx = centers[i * 3], cy = centers[i * 3 + 1], cz = centers[i * 3 + 2];
        float rad = radii[i];

        float* s = shc + i * 28;
        #pragma unroll
        for (int r = 0; r < 3; ++r) {
            float cs3[4] = {T[r][0], T[r][1], T[r][2],
                            (r == 0 ? -cx : (r == 1 ? -cy : -cz))};
            #pragma unroll
            for (int c = 0; c < 4; ++c) {
                s[(r * 4 + c) * 2]     = cs3[c];
                s[(r * 4 + c) * 2 + 1] = cs3[c];
            }
        }
        float b = 46.16624130844683f * rad;  // 32*log2(e)*r
        s[24] = b; s[25] = b; s[26] = 0.f; s[27] = 0.f;

        // sigma_min lower bound: lambda_min(T^T T) >= q - 2*sqrt(p2/6)
        float M00 = 0, M11 = 0, M22 = 0, M01 = 0, M02 = 0, M12 = 0;
        #pragma unroll
        for (int k = 0; k < 3; ++k) {
            float t0 = T[k][0], t1 = T[k][1], t2 = T[k][2];
            M00 = fmaf(t0, t0, M00); M11 = fmaf(t1, t1, M11); M22 = fmaf(t2, t2, M22);
            M01 = fmaf(t0, t1, M01); M02 = fmaf(t0, t2, M02); M12 = fmaf(t1, t2, M12);
        }
        float q  = (M00 + M11 + M22) * (1.0f / 3.0f);
        float a0 = M00 - q, a1 = M11 - q, a2 = M22 - q;
        float p2 = a0 * a0 + a1 * a1 + a2 * a2
                 + 2.0f * (M01 * M01 + M02 * M02 + M12 * M12);
        float lmin = q - 2.001f * sqrtf(fmaxf(p2, 0.0f) * (1.0f / 6.0f)) - 1e-6f;
        float sig  = sqrtf(fmaxf(lmin, 0.0f)) * 0.999f;
        float cn   = sqrtf(cx * cx + cy * cy + cz * cz) * 1.0001f + 1e-7f;
        float num  = 0.601f + cn + rad;   // 0.601 > (ln128+ln1e6)/32 = 0.5834
        float thr2 = 1e30f;               // sig~0 => no culling (still correct)
        if (sig > 1e-6f) {
            float thr = num / sig;
            thr2 = thr * thr * 1.002f;
        }
        atomicMax(&s_thr2_bits, __float_as_int(thr2));
    }
    __syncthreads();
    float R2 = __int_as_float(s_thr2_bits);

    // ---- phase B: classify 8 points, compact near ones into shared ----
    float x[8], y[8], z[8];
    bool nearf[8];
    #pragma unroll
    for (int k = 0; k < 8; ++k) nearf[k] = false;
    int cnt = 0;
    if (inb) {
        x[0]=f[0].x; y[0]=f[0].y; z[0]=f[0].z;
        x[1]=f[0].w; y[1]=f[1].x; z[1]=f[1].y;
        x[2]=f[1].z; y[2]=f[1].w; z[2]=f[2].x;
        x[3]=f[2].y; y[3]=f[2].z; z[3]=f[2].w;
        x[4]=f[3].x; y[4]=f[3].y; z[4]=f[3].z;
        x[5]=f[3].w; y[5]=f[4].x; z[5]=f[4].y;
        x[6]=f[4].z; y[6]=f[4].w; z[6]=f[5].x;
        x[7]=f[5].y; y[7]=f[5].z; z[7]=f[5].w;
        #pragma unroll
        for (int k = 0; k < 8; ++k) {
            float n2 = fmaf(x[k], x[k], fmaf(y[k], y[k], z[k] * z[k]));
            nearf[k] = n2 < R2;
            if (!nearf[k]) out[base + k] = FASTVAL;
            cnt += nearf[k] ? 1 : 0;
        }
    } else if (base < npts) {
        // generic tail (not hit for npts % 2048 == 0): scalar slow path
        for (int k = 0; k < 8 && base + k < npts; ++k) {
            float xx = p[(base + k) * 3], yy = p[(base + k) * 3 + 1], zz = p[(base + k) * 3 + 2];
            float ssum = 0.f;
            for (int i = 0; i < N_SPH; ++i) {
                const float* s = shc + i * 28;
                float qx = fmaf(s[0], xx, fmaf(s[2],  yy, fmaf(s[4],  zz, s[6])));
                float qy = fmaf(s[8], xx, fmaf(s[10], yy, fmaf(s[12], zz, s[14])));
                float qz = fmaf(s[16], xx, fmaf(s[18], yy, fmaf(s[20], zz, s[22])));
                float d2 = fmaf(qx, qx, fmaf(qy, qy, qz * qz));
                ssum += ex2_ap(fmaf(sqrt_ap(d2), -46.16624130844683f, s[24]));
            }
            out[base + k] = lg2_ap(fmaxf(ssum, 1e-6f)) * -0.021660849392498290f;
        }
    }
    unsigned mask = 0xffffffffu;
    int lane = tid & 31;
    int incl = cnt;
    #pragma unroll
    for (int d = 1; d < 32; d <<= 1) {
        int v = __shfl_up_sync(mask, incl, d);
        if (lane >= d) incl += v;
    }
    int wtotal = __shfl_sync(mask, incl, 31);
    int wbase = 0;
    if (lane == 0) wbase = (wtotal > 0) ? atomicAdd(&s_count, wtotal) : 0;
    wbase = __shfl_sync(mask, wbase, 0);
    int off = wbase + incl - cnt;
    #pragma unroll
    for (int k = 0; k < 8; ++k) {
        if (nearf[k]) {
            if (off < CAP) {
                sbuf[off] = make_float4(x[k], y[k], z[k], __int_as_float(base + k));
            } else {
                // overflow slow path (only if culling degrades): scalar, correct
                float ssum = 0.f;
                for (int i = 0; i < N_SPH; ++i) {
                    const float* s = shc + i * 28;
                    float qx = fmaf(s[0], x[k], fmaf(s[2],  y[k], fmaf(s[4],  z[k], s[6])));
                    float qy = fmaf(s[8], x[k], fmaf(s[10], y[k], fmaf(s[12], z[k], s[14])));
                    float qz = fmaf(s[16], x[k], fmaf(s[18], y[k], fmaf(s[20], z[k], s[22])));
                    float d2 = fmaf(qx, qx, fmaf(qy, qy, qz * qz));
                    ssum += ex2_ap(fmaf(sqrt_ap(d2), -46.16624130844683f, s[24]));
                }
                out[base + k] = lg2_ap(fmaxf(ssum, 1e-6f)) * -0.021660849392498290f;
            }
            off++;
        }
    }
    __syncthreads();

    // ---- phase C: unit = (pair j, group g of 16 spheres) ----
    // WARP-UNIFORM g (broadcast const loads): j = (u>>8)*32 + (u&31), g = (u>>5)&7
    int count = min(s_count, CAP);
    int pairs = (count + 1) >> 1;
    int total_u = ((pairs + 31) >> 5) << 8;   // pairs rounded to 32, x8 groups

    for (int u = tid; u < total_u; u += 256) {
        int j = ((u >> 8) << 5) | (u & 31);
        int g = (u >> 5) & 7;
        if (j >= pairs) continue;

        int ia = 2 * j;
        int ib = min(2 * j + 1, count - 1);
        float4 A = sbuf[ia];
        float4 B = sbuf[ib];

        u64 X = pk2(A.x, B.x), Y = pk2(A.y, B.y), Z = pk2(A.z, B.z);
        float s0 = 0.f, s1 = 0.f;

        const float* cb = shc + g * (16 * 28);
        #pragma unroll 4
        for (int sp = 0; sp < 16; ++sp) {
            const ulonglong2* C = reinterpret_cast<const ulonglong2*>(cb + sp * 28);
            ulonglong2 m0 = C[0];  // (t00, t01)
            ulonglong2 m1 = C[1];  // (t02, -cx)
            ulonglong2 m2 = C[2];  // (t10, t11)
            ulonglong2 m3 = C[3];  // (t12, -cy)
            ulonglong2 m4 = C[4];  // (t20, t21)
            ulonglong2 m5 = C[5];  // (t22, -cz)
            u64 bb = reinterpret_cast<const u64*>(C)[12];

            u64 qx = f2fma(m0.x, X, f2fma(m0.y, Y, f2fma(m1.x, Z, m1.y)));
            u64 qy = f2fma(m2.x, X, f2fma(m2.y, Y, f2fma(m3.x, Z, m3.y)));
            u64 qz = f2fma(m4.x, X, f2fma(m4.y, Y, f2fma(m5.x, Z, m5.y)));
            u64 d2 = f2fma(qx, qx, f2fma(qy, qy, f2mul(qz, qz)));

            float2 d  = up2(d2);
            float2 bs = up2(bb);
            s0 += ex2_ap(fmaf(sqrt_ap(d.x), -46.16624130844683f, bs.x));
            s1 += ex2_ap(fmaf(sqrt_ap(d.y), -46.16624130844683f, bs.y));
        }

        spart[g * (CAP + 1) + ia] = s0;
        if (2 * j + 1 < count) spart[g * (CAP + 1) + ib] = s1;
    }
    __syncthreads();

    // ---- phase D: fixed-order combine of 8 group partials per point ----
    const float NEG_LN2_32 = -0.021660849392498290f;
    for (int pt = tid; pt < count; pt += 256) {
        float acc[8];
        #pragma unroll
        for (int g = 0; g < 8; ++g) acc[g] = spart[g * (CAP + 1) + pt];
        float s = ((acc[0] + acc[1]) + (acc[2] + acc[3]))
                + ((acc[4] + acc[5]) + (acc[6] + acc[7]));
        out[__float_as_int(sbuf[pt].w)] = lg2_ap(fmaxf(s, 1e-6f)) * NEG_LN2_32;
    }
}

extern "C" void kernel_launch(void* const* d_in, const int* in_sizes, int n_in,
                              void* d_out, int out_size) {
    const float* p       = (const float*)d_in[0];
    const float* centers = (const float*)d_in[1];
    const float* radii   = (const float*)d_in[2];
    const float* tfs     = (const float*)d_in[3];
    float* out = (float*)d_out;

    int npts = in_sizes[0] / 3;
    int blocks = (npts + PPB - 1) / PPB;   // 512 blocks for 1M points -> one wave
    smoothed_fused<<<blocks, 256>>>(p, centers, radii, tfs, out, npts);
}

// round 11
// speedup vs baseline: 1.3085x; 1.3085x over previous
#include <cuda_runtime.h>

#define N_SPH 128
#define CAP   256          // per-block compaction capacity (overflow -> slow path)
typedef unsigned long long u64;

// -ln(1e-6)/32 : exact output when s clamps at 1e-6
#define FASTVAL 0.4317347049363836f

// ---- packed f32x2 helpers (sm_100+) ----
__device__ __forceinline__ u64 pk2(float lo, float hi) {
    u64 r; asm("mov.b64 %0, {%1, %2};" : "=l"(r) : "f"(lo), "f"(hi)); return r;
}
__device__ __forceinline__ float2 up2(u64 v) {
    float2 f; asm("mov.b64 {%0, %1}, %2;" : "=f"(f.x), "=f"(f.y) : "l"(v)); return f;
}
__device__ __forceinline__ u64 f2fma(u64 a, u64 b, u64 c) {
    u64 d; asm("fma.rn.f32x2 %0, %1, %2, %3;" : "=l"(d) : "l"(a), "l"(b), "l"(c)); return d;
}
__device__ __forceinline__ u64 f2mul(u64 a, u64 b) {
    u64 d; asm("mul.rn.f32x2 %0, %1, %2;" : "=l"(d) : "l"(a), "l"(b)); return d;
}
__device__ __forceinline__ float sqrt_ap(float x) {
    float r; asm("sqrt.approx.f32 %0, %1;" : "=f"(r) : "f"(x)); return r;
}
__device__ __forceinline__ float ex2_ap(float x) {
    float r; asm("ex2.approx.f32 %0, %1;" : "=f"(r) : "f"(x)); return r;
}
__device__ __forceinline__ float lg2_ap(float x) {
    float r; asm("lg2.approx.f32 %0, %1;" : "=f"(r) : "f"(x)); return r;
}

__global__ void __launch_bounds__(256, 5) smoothed_fused(
    const float* __restrict__ p,
    const float* __restrict__ centers,
    const float* __restrict__ radii,
    const float* __restrict__ tfs,
    float* __restrict__ out, int npts) {

    __shared__ __align__(16) float  shc[N_SPH * 28];        // 14336 B packed consts
    __shared__ __align__(16) float4 sbuf[CAP];              //  4096 B compacted points
    __shared__ float  spart[8 * 257];                       //  8224 B partials / reductions
    __shared__ float  s_R2;
    __shared__ int    s_count;

    const int tid = threadIdx.x;
    if (tid == 0) s_count = 0;

    // reduction scratch aliased onto spart (free until phase C)
    float* red_sum = spart;          // [0..127]  : exp(32*a_i) terms
    float* red_sig = spart + 128;    // [128..255]: sigma_min lower bounds

    // ---- prefetch this thread's 4 points ----
    int t = blockIdx.x * 256 + tid;
    int base = t * 4;
    float4 va, vb, vc;
    bool inb = base < npts;
    if (inb) {
        const float4* p4 = reinterpret_cast<const float4*>(p);
        int f = t * 3;
        va = p4[f]; vb = p4[f + 1]; vc = p4[f + 2];
    }

    // ---- phase A: threads 0..127 build sphere consts + LSE threshold terms ----
    if (tid < N_SPH) {
        int i = tid;
        float T[3][3];
        #pragma unroll
        for (int r = 0; r < 3; ++r)
            #pragma unroll
            for (int c = 0; c < 3; ++c)
                T[r][c] = tfs[i * 9 + r * 3 + c] + ((r == c) ? 1.0f : 0.0f);
        float cx = centers[i * 3], cy = centers[i * 3 + 1], cz = centers[i * 3 + 2];
        float rad = radii[i];

        float* s = shc + i * 28;
        #pragma unroll
        for (int r = 0; r < 3; ++r) {
            float cs3[4] = {T[r][0], T[r][1], T[r][2],
                            (r == 0 ? -cx : (r == 1 ? -cy : -cz))};
            #pragma unroll
            for (int c = 0; c < 4; ++c) {
                s[(r * 4 + c) * 2]     = cs3[c];
                s[(r * 4 + c) * 2 + 1] = cs3[c];
            }
        }
        float b = 46.16624130844683f * rad;  // 32*log2(e)*r
        s[24] = b; s[25] = b; s[26] = 0.f; s[27] = 0.f;

        // sigma_min lower bound: lambda_min(T^T T) >= q - 2*sqrt(p2/6)
        float M00 = 0, M11 = 0, M22 = 0, M01 = 0, M02 = 0, M12 = 0;
        #pragma unroll
        for (int k = 0; k < 3; ++k) {
            float t0 = T[k][0], t1 = T[k][1], t2 = T[k][2];
            M00 = fmaf(t0, t0, M00); M11 = fmaf(t1, t1, M11); M22 = fmaf(t2, t2, M22);
            M01 = fmaf(t0, t1, M01); M02 = fmaf(t0, t2, M02); M12 = fmaf(t1, t2, M12);
        }
        float q  = (M00 + M11 + M22) * (1.0f / 3.0f);
        float a0 = M00 - q, a1 = M11 - q, a2 = M22 - q;
        float p2 = a0 * a0 + a1 * a1 + a2 * a2
                 + 2.0f * (M01 * M01 + M02 * M02 + M12 * M12);
        float lmin = q - 2.001f * sqrtf(fmaxf(p2, 0.0f) * (1.0f / 6.0f)) - 1e-6f;
        float sig  = sqrtf(fmaxf(lmin, 0.0f)) * 0.999f;   // one-sided lower bound

        // LSE term: a_i = ||c_i|| + r_i (upper bound, inflated)
        float cn = sqrtf(cx * cx + cy * cy + cz * cz) * 1.0002f + 1e-7f;
        float a  = cn + rad;
        red_sum[i] = expf(32.0f * a);   // inf on overflow -> no culling (safe)
        red_sig[i] = sig;
    }
    __syncthreads();

    // tree reduce: sum of exp terms, min of sigmas (threads 0..63 etc.)
    for (int stp = 64; stp; stp >>= 1) {
        if (tid < stp) {
            red_sum[tid] = red_sum[tid] + red_sum[tid + stp];
            red_sig[tid] = fminf(red_sig[tid], red_sig[tid + stp]);
        }
        __syncthreads();
    }
    if (tid == 0) {
        float S    = red_sum[0] * 1.01f;            // safety inflate
        float sigg = red_sig[0];
        float thr2 = 1e30f;                          // default: no culling
        if (sigg > 1e-6f && !(S != S)) {             // S NaN-guard
            // R = (ln S + ln 1e6 + delta) / (32*sig); cull if ||p|| > R
            float Rnum = logf(S) + 13.8155106f + 0.03f;
            if (Rnum <= 0.0f) {
                thr2 = 0.0f;                         // everything clamps: cull all
            } else if (Rnum < 1e15f) {               // excludes inf (S overflow)
                float R = Rnum / (32.0f * sigg);
                thr2 = R * R * 1.002f;
            }
        }
        s_R2 = thr2;
    }
    __syncthreads();
    float R2 = s_R2;

    // ---- phase B: classify, compact into shared (cap CAP), overflow slow path ----
    float x[4], y[4], z[4];
    bool nearf[4] = {false, false, false, false};
    int cnt = 0;
    if (inb) {
        x[0] = va.x; y[0] = va.y; z[0] = va.z;
        x[1] = va.w; y[1] = vb.x; z[1] = vb.y;
        x[2] = vb.z; y[2] = vb.w; z[2] = vc.x;
        x[3] = vc.y; y[3] = vc.z; z[3] = vc.w;
        #pragma unroll
        for (int k = 0; k < 4; ++k) {
            float n2 = fmaf(x[k], x[k], fmaf(y[k], y[k], z[k] * z[k]));
            nearf[k] = n2 < R2;
            if (!nearf[k]) out[base + k] = FASTVAL;
            cnt += nearf[k] ? 1 : 0;
        }
    }
    unsigned mask = 0xffffffffu;
    int lane = tid & 31;
    int incl = cnt;
    #pragma unroll
    for (int d = 1; d < 32; d <<= 1) {
        int v = __shfl_up_sync(mask, incl, d);
        if (lane >= d) incl += v;
    }
    int total = __shfl_sync(mask, incl, 31);
    int wbase = 0;
    if (lane == 0) wbase = (total > 0) ? atomicAdd(&s_count, total) : 0;
    wbase = __shfl_sync(mask, wbase, 0);
    int off = wbase + incl - cnt;
    #pragma unroll
    for (int k = 0; k < 4; ++k) {
        if (nearf[k]) {
            if (off < CAP) {
                sbuf[off] = make_float4(x[k], y[k], z[k], __int_as_float(base + k));
            } else {
                // overflow slow path: full scalar loop (correct, rare)
                float ssum = 0.f;
                for (int i = 0; i < N_SPH; ++i) {
                    const float* s = shc + i * 28;
                    float qx = fmaf(s[0], x[k], fmaf(s[2],  y[k], fmaf(s[4],  z[k], s[6])));
                    float qy = fmaf(s[8], x[k], fmaf(s[10], y[k], fmaf(s[12], z[k], s[14])));
                    float qz = fmaf(s[16], x[k], fmaf(s[18], y[k], fmaf(s[20], z[k], s[22])));
                    float d2 = fmaf(qx, qx, fmaf(qy, qy, qz * qz));
                    ssum += ex2_ap(fmaf(sqrt_ap(d2), -46.16624130844683f, s[24]));
                }
                out[base + k] = lg2_ap(fmaxf(ssum, 1e-6f)) * -0.021660849392498290f;
            }
            off++;
        }
    }
    __syncthreads();

    // ---- phase C: unit = (pair j, group g of 16 spheres) ----
    // WARP-UNIFORM g (broadcast const loads): j = (u>>8)*32 + (u&31), g = (u>>5)&7
    int count = min(s_count, CAP);
    int pairs = (count + 1) >> 1;
    int total_u = ((pairs + 31) >> 5) << 8;   // pairs rounded to 32, x8 groups

    for (int u = tid; u < total_u; u += 256) {
        int j = ((u >> 8) << 5) | (u & 31);
        int g = (u >> 5) & 7;
        if (j >= pairs) continue;

        int ia = 2 * j;
        int ib = min(2 * j + 1, count - 1);
        float4 A = sbuf[ia];
        float4 B = sbuf[ib];

        u64 X = pk2(A.x, B.x), Y = pk2(A.y, B.y), Z = pk2(A.z, B.z);
        float s0 = 0.f, s1 = 0.f;

        const float* cb = shc + g * (16 * 28);
        #pragma unroll 4
        for (int sp = 0; sp < 16; ++sp) {
            const ulonglong2* C = reinterpret_cast<const ulonglong2*>(cb + sp * 28);
            ulonglong2 m0 = C[0];  // (t00, t01)
            ulonglong2 m1 = C[1];  // (t02, -cx)
            ulonglong2 m2 = C[2];  // (t10, t11)
            ulonglong2 m3 = C[3];  // (t12, -cy)
            ulonglong2 m4 = C[4];  // (t20, t21)
            ulonglong2 m5 = C[5];  // (t22, -cz)
            u64 bb = reinterpret_cast<const u64*>(C)[12];

            u64 qx = f2fma(m0.x, X, f2fma(m0.y, Y, f2fma(m1.x, Z, m1.y)));
            u64 qy = f2fma(m2.x, X, f2fma(m2.y, Y, f2fma(m3.x, Z, m3.y)));
            u64 qz = f2fma(m4.x, X, f2fma(m4.y, Y, f2fma(m5.x, Z, m5.y)));
            u64 d2 = f2fma(qx, qx, f2fma(qy, qy, f2mul(qz, qz)));

            float2 d  = up2(d2);
            float2 bs = up2(bb);
            s0 += ex2_ap(fmaf(sqrt_ap(d.x), -46.16624130844683f, bs.x));
            s1 += ex2_ap(fmaf(sqrt_ap(d.y), -46.16624130844683f, bs.y));
        }

        spart[g * 257 + ia] = s0;
        if (2 * j + 1 < count) spart[g * 257 + ib] = s1;
    }
    __syncthreads();

    // ---- phase D: fixed-order combine of 8 group partials per point ----
    const float NEG_LN2_32 = -0.021660849392498290f;
    for (int pt = tid; pt < count; pt += 256) {
        float acc[8];
        #pragma unroll
        for (int g = 0; g < 8; ++g) acc[g] = spart[g * 257 + pt];
        float s = ((acc[0] + acc[1]) + (acc[2] + acc[3]))
                + ((acc[4] + acc[5]) + (acc[6] + acc[7]));
        out[__float_as_int(sbuf[pt].w)] = lg2_ap(fmaxf(s, 1e-6f)) * NEG_LN2_32;
    }
}

extern "C" void kernel_launch(void* const* d_in, const int* in_sizes, int n_in,
                              void* d_out, int out_size) {
    const float* p       = (const float*)d_in[0];
    const float* centers = (const float*)d_in[1];
    const float* radii   = (const float*)d_in[2];
    const float* tfs     = (const float*)d_in[3];
    float* out = (float*)d_out;

    int npts = in_sizes[0] / 3;
    int blocks = (npts + 1023) / 1024;  // 256 threads x 4 points
    smoothed_fused<<<blocks, 256>>>(p, centers, radii, tfs, out, npts);
}

// round 12
// speedup vs baseline: 1.6440x; 1.2564x over previous
#include <cuda_runtime.h>

#define N_SPH 128
#define CAP   256          // per-block compaction capacity (overflow -> slow path)
typedef unsigned long long u64;

// -ln(1e-6)/32 : exact output when s clamps at 1e-6
#define FASTVAL 0.4317347049363836f

// ---- packed f32x2 helpers (sm_100+) ----
__device__ __forceinline__ u64 pk2(float lo, float hi) {
    u64 r; asm("mov.b64 %0, {%1, %2};" : "=l"(r) : "f"(lo), "f"(hi)); return r;
}
__device__ __forceinline__ float2 up2(u64 v) {
    float2 f; asm("mov.b64 {%0, %1}, %2;" : "=f"(f.x), "=f"(f.y) : "l"(v)); return f;
}
__device__ __forceinline__ u64 f2fma(u64 a, u64 b, u64 c) {
    u64 d; asm("fma.rn.f32x2 %0, %1, %2, %3;" : "=l"(d) : "l"(a), "l"(b), "l"(c)); return d;
}
__device__ __forceinline__ u64 f2mul(u64 a, u64 b) {
    u64 d; asm("mul.rn.f32x2 %0, %1, %2;" : "=l"(d) : "l"(a), "l"(b)); return d;
}
__device__ __forceinline__ u64 f2add(u64 a, u64 b) {
    u64 d; asm("add.rn.f32x2 %0, %1, %2;" : "=l"(d) : "l"(a), "l"(b)); return d;
}
__device__ __forceinline__ float sqrt_ap(float x) {
    float r; asm("sqrt.approx.f32 %0, %1;" : "=f"(r) : "f"(x)); return r;
}
__device__ __forceinline__ float ex2_ap(float x) {
    float r; asm("ex2.approx.f32 %0, %1;" : "=f"(r) : "f"(x)); return r;
}
__device__ __forceinline__ float lg2_ap(float x) {
    float r; asm("lg2.approx.f32 %0, %1;" : "=f"(r) : "f"(x)); return r;
}

__global__ void __launch_bounds__(256, 5) smoothed_fused(
    const float* __restrict__ p,
    const float* __restrict__ centers,
    const float* __restrict__ radii,
    const float* __restrict__ tfs,
    float* __restrict__ out, int npts) {

    __shared__ __align__(16) float  shc[N_SPH * 28];   // 14336 B general consts
    __shared__ __align__(16) float  shc2[N_SPH * 8];   //  4096 B identity consts
    __shared__ __align__(16) float4 sbuf[CAP];         //  4096 B compacted points
    __shared__ float  spart[8 * 257];                  //  8224 B partials / reductions
    __shared__ float  s_R2;
    __shared__ int    s_count;
    __shared__ int    s_ident;

    const int tid = threadIdx.x;
    if (tid == 0) { s_count = 0; s_ident = 1; }

    // reduction scratch aliased onto spart (free until phase C)
    float* red_sum = spart;          // [0..127]  : exp(32*a_i) terms
    float* red_sig = spart + 128;    // [128..255]: sigma_min lower bounds

    // ---- prefetch this thread's 4 points ----
    int t = blockIdx.x * 256 + tid;
    int base = t * 4;
    float4 va, vb, vc;
    bool inb = base < npts;
    if (inb) {
        const float4* p4 = reinterpret_cast<const float4*>(p);
        int f = t * 3;
        va = p4[f]; vb = p4[f + 1]; vc = p4[f + 2];
    }
    __syncthreads();   // s_count / s_ident init visible

    // ---- phase A: threads 0..127 build consts + LSE threshold terms ----
    if (tid < N_SPH) {
        int i = tid;
        float T[3][3];
        bool ident = true;
        #pragma unroll
        for (int r = 0; r < 3; ++r)
            #pragma unroll
            for (int c = 0; c < 3; ++c) {
                float tv = tfs[i * 9 + r * 3 + c];
                if (tv != 0.0f) ident = false;
                T[r][c] = tv + ((r == c) ? 1.0f : 0.0f);
            }
        if (!ident) atomicAnd(&s_ident, 0);

        float cx = centers[i * 3], cy = centers[i * 3 + 1], cz = centers[i * 3 + 2];
        float rad = radii[i];
        float b = 46.16624130844683f * rad;  // 32*log2(e)*r

        float* s = shc + i * 28;
        #pragma unroll
        for (int r = 0; r < 3; ++r) {
            float cs3[4] = {T[r][0], T[r][1], T[r][2],
                            (r == 0 ? -cx : (r == 1 ? -cy : -cz))};
            #pragma unroll
            for (int c = 0; c < 4; ++c) {
                s[(r * 4 + c) * 2]     = cs3[c];
                s[(r * 4 + c) * 2 + 1] = cs3[c];
            }
        }
        s[24] = b; s[25] = b; s[26] = 0.f; s[27] = 0.f;

        // identity consts: [ncx ncx ncy ncy ncz ncz b b]
        float* s2 = shc2 + i * 8;
        s2[0] = -cx; s2[1] = -cx;
        s2[2] = -cy; s2[3] = -cy;
        s2[4] = -cz; s2[5] = -cz;
        s2[6] = b;   s2[7] = b;

        // sigma_min lower bound: lambda_min(T^T T) >= q - 2*sqrt(p2/6)
        float M00 = 0, M11 = 0, M22 = 0, M01 = 0, M02 = 0, M12 = 0;
        #pragma unroll
        for (int k = 0; k < 3; ++k) {
            float t0 = T[k][0], t1 = T[k][1], t2 = T[k][2];
            M00 = fmaf(t0, t0, M00); M11 = fmaf(t1, t1, M11); M22 = fmaf(t2, t2, M22);
            M01 = fmaf(t0, t1, M01); M02 = fmaf(t0, t2, M02); M12 = fmaf(t1, t2, M12);
        }
        float q  = (M00 + M11 + M22) * (1.0f / 3.0f);
        float a0 = M00 - q, a1 = M11 - q, a2 = M22 - q;
        float p2 = a0 * a0 + a1 * a1 + a2 * a2
                 + 2.0f * (M01 * M01 + M02 * M02 + M12 * M12);
        float lmin = q - 2.001f * sqrtf(fmaxf(p2, 0.0f) * (1.0f / 6.0f)) - 1e-6f;
        float sig  = sqrtf(fmaxf(lmin, 0.0f)) * 0.999f;   // one-sided lower bound

        // LSE term: a_i = ||c_i|| + r_i (upper bound, inflated)
        float cn = sqrtf(cx * cx + cy * cy + cz * cz) * 1.0002f + 1e-7f;
        float a  = cn + rad;
        red_sum[i] = expf(32.0f * a);   // inf on overflow -> no culling (safe)
        red_sig[i] = sig;
    }
    __syncthreads();

    // tree reduce: sum of exp terms, min of sigmas
    for (int stp = 64; stp; stp >>= 1) {
        if (tid < stp) {
            red_sum[tid] = red_sum[tid] + red_sum[tid + stp];
            red_sig[tid] = fminf(red_sig[tid], red_sig[tid + stp]);
        }
        __syncthreads();
    }
    if (tid == 0) {
        float S    = red_sum[0] * 1.01f;            // safety inflate
        float sigg = red_sig[0];
        float thr2 = 1e30f;                          // default: no culling
        if (sigg > 1e-6f && !(S != S)) {             // S NaN-guard
            float Rnum = logf(S) + 13.8155106f + 0.03f;   // ln S + ln 1e6 + delta
            if (Rnum <= 0.0f) {
                thr2 = 0.0f;                         // everything clamps: cull all
            } else if (Rnum < 1e15f) {               // excludes inf (S overflow)
                float R = Rnum / (32.0f * sigg);
                thr2 = R * R * 1.002f;
            }
        }
        s_R2 = thr2;
    }
    __syncthreads();
    float R2 = s_R2;
    int ident = s_ident;

    // ---- phase B: classify, compact into shared (cap CAP), overflow slow path ----
    float x[4], y[4], z[4];
    bool nearf[4] = {false, false, false, false};
    int cnt = 0;
    if (inb) {
        x[0] = va.x; y[0] = va.y; z[0] = va.z;
        x[1] = va.w; y[1] = vb.x; z[1] = vb.y;
        x[2] = vb.z; y[2] = vb.w; z[2] = vc.x;
        x[3] = vc.y; y[3] = vc.z; z[3] = vc.w;
        #pragma unroll
        for (int k = 0; k < 4; ++k) {
            float n2 = fmaf(x[k], x[k], fmaf(y[k], y[k], z[k] * z[k]));
            nearf[k] = n2 < R2;
            if (!nearf[k]) out[base + k] = FASTVAL;
            cnt += nearf[k] ? 1 : 0;
        }
    }
    unsigned mask = 0xffffffffu;
    int lane = tid & 31;
    int incl = cnt;
    #pragma unroll
    for (int d = 1; d < 32; d <<= 1) {
        int v = __shfl_up_sync(mask, incl, d);
        if (lane >= d) incl += v;
    }
    int total = __shfl_sync(mask, incl, 31);
    int wbase = 0;
    if (lane == 0) wbase = (total > 0) ? atomicAdd(&s_count, total) : 0;
    wbase = __shfl_sync(mask, wbase, 0);
    int off = wbase + incl - cnt;
    #pragma unroll
    for (int k = 0; k < 4; ++k) {
        if (nearf[k]) {
            if (off < CAP) {
                sbuf[off] = make_float4(x[k], y[k], z[k], __int_as_float(base + k));
            } else {
                // overflow slow path: full scalar loop (correct, rare)
                float ssum = 0.f;
                for (int i = 0; i < N_SPH; ++i) {
                    const float* s = shc + i * 28;
                    float qx = fmaf(s[0], x[k], fmaf(s[2],  y[k], fmaf(s[4],  z[k], s[6])));
                    float qy = fmaf(s[8], x[k], fmaf(s[10], y[k], fmaf(s[12], z[k], s[14])));
                    float qz = fmaf(s[16], x[k], fmaf(s[18], y[k], fmaf(s[20], z[k], s[22])));
                    float d2 = fmaf(qx, qx, fmaf(qy, qy, qz * qz));
                    ssum += ex2_ap(fmaf(sqrt_ap(d2), -46.16624130844683f, s[24]));
                }
                out[base + k] = lg2_ap(fmaxf(ssum, 1e-6f)) * -0.021660849392498290f;
            }
            off++;
        }
    }
    __syncthreads();

    // ---- phase C: unit = (pair j, group g of 16 spheres) ----
    // WARP-UNIFORM g (broadcast const loads): j = (u>>8)*32 + (u&31), g = (u>>5)&7
    int count = min(s_count, CAP);
    int pairs = (count + 1) >> 1;
    int total_u = ((pairs + 31) >> 5) << 8;   // pairs rounded to 32, x8 groups

    for (int u = tid; u < total_u; u += 256) {
        int j = ((u >> 8) << 5) | (u & 31);
        int g = (u >> 5) & 7;
        if (j >= pairs) continue;

        int ia = 2 * j;
        int ib = min(2 * j + 1, count - 1);
        float4 A = sbuf[ia];
        float4 B = sbuf[ib];

        u64 X = pk2(A.x, B.x), Y = pk2(A.y, B.y), Z = pk2(A.z, B.z);
        float s0 = 0.f, s1 = 0.f;

        if (ident) {
            // identity T: q = p - c  (bit-identical to the general path when T=I)
            const float* cb2 = shc2 + g * (16 * 8);
            #pragma unroll 4
            for (int sp = 0; sp < 16; ++sp) {
                const ulonglong2* C = reinterpret_cast<const ulonglong2*>(cb2 + sp * 8);
                ulonglong2 n0 = C[0];  // (ncx, ncy)
                ulonglong2 n1 = C[1];  // (ncz, b)

                u64 qx = f2add(X, n0.x);
                u64 qy = f2add(Y, n0.y);
                u64 qz = f2add(Z, n1.x);
                u64 d2 = f2fma(qx, qx, f2fma(qy, qy, f2mul(qz, qz)));

                float2 d  = up2(d2);
                float2 bs = up2(n1.y);
                s0 += ex2_ap(fmaf(sqrt_ap(d.x), -46.16624130844683f, bs.x));
                s1 += ex2_ap(fmaf(sqrt_ap(d.y), -46.16624130844683f, bs.y));
            }
        } else {
            const float* cb = shc + g * (16 * 28);
            #pragma unroll 4
            for (int sp = 0; sp < 16; ++sp) {
                const ulonglong2* C = reinterpret_cast<const ulonglong2*>(cb + sp * 28);
                ulonglong2 m0 = C[0], m1 = C[1], m2 = C[2];
                ulonglong2 m3 = C[3], m4 = C[4], m5 = C[5];
                u64 bb = reinterpret_cast<const u64*>(C)[12];

                u64 qx = f2fma(m0.x, X, f2fma(m0.y, Y, f2fma(m1.x, Z, m1.y)));
                u64 qy = f2fma(m2.x, X, f2fma(m2.y, Y, f2fma(m3.x, Z, m3.y)));
                u64 qz = f2fma(m4.x, X, f2fma(m4.y, Y, f2fma(m5.x, Z, m5.y)));
                u64 d2 = f2fma(qx, qx, f2fma(qy, qy, f2mul(qz, qz)));

                float2 d  = up2(d2);
                float2 bs = up2(bb);
                s0 += ex2_ap(fmaf(sqrt_ap(d.x), -46.16624130844683f, bs.x));
                s1 += ex2_ap(fmaf(sqrt_ap(d.y), -46.16624130844683f, bs.y));
            }
        }

        spart[g * 257 + ia] = s0;
        if (2 * j + 1 < count) spart[g * 257 + ib] = s1;
    }
    __syncthreads();

    // ---- phase D: fixed-order combine of 8 group partials per point ----
    const float NEG_LN2_32 = -0.021660849392498290f;
    for (int pt = tid; pt < count; pt += 256) {
        float acc[8];
        #pragma unroll
        for (int g = 0; g < 8; ++g) acc[g] = spart[g * 257 + pt];
        float s = ((acc[0] + acc[1]) + (acc[2] + acc[3]))
                + ((acc[4] + acc[5]) + (acc[6] + acc[7]));
        out[__float_as_int(sbuf[pt].w)] = lg2_ap(fmaxf(s, 1e-6f)) * NEG_LN2_32;
    }
}

extern "C" void kernel_launch(void* const* d_in, const int* in_sizes, int n_in,
                              void* d_out, int out_size) {
    const float* p       = (const float*)d_in[0];
    const float* centers = (const float*)d_in[1];
    const float* radii   = (const float*)d_in[2];
    const float* tfs     = (const float*)d_in[3];
    float* out = (float*)d_out;

    int npts = in_sizes[0] / 3;
    int blocks = (npts + 1023) / 1024;  // 256 threads x 4 points
    smoothed_fused<<<blocks, 256>>>(p, centers, radii, tfs, out, npts);
}

// round 13
// speedup vs baseline: 1.6952x; 1.0311x over previous
#include <cuda_runtime.h>

#define N_SPH 128
#define CAP   256          // per-block compaction capacity (overflow -> slow path)
typedef unsigned long long u64;

// -ln(1e-6)/32 : exact output when s clamps at 1e-6
#define FASTVAL 0.4317347049363836f

// ---- packed f32x2 helpers (sm_100+) ----
__device__ __forceinline__ u64 pk2(float lo, float hi) {
    u64 r; asm("mov.b64 %0, {%1, %2};" : "=l"(r) : "f"(lo), "f"(hi)); return r;
}
__device__ __forceinline__ float2 up2(u64 v) {
    float2 f; asm("mov.b64 {%0, %1}, %2;" : "=f"(f.x), "=f"(f.y) : "l"(v)); return f;
}
__device__ __forceinline__ u64 f2fma(u64 a, u64 b, u64 c) {
    u64 d; asm("fma.rn.f32x2 %0, %1, %2, %3;" : "=l"(d) : "l"(a), "l"(b), "l"(c)); return d;
}
__device__ __forceinline__ u64 f2mul(u64 a, u64 b) {
    u64 d; asm("mul.rn.f32x2 %0, %1, %2;" : "=l"(d) : "l"(a), "l"(b)); return d;
}
__device__ __forceinline__ u64 f2add(u64 a, u64 b) {
    u64 d; asm("add.rn.f32x2 %0, %1, %2;" : "=l"(d) : "l"(a), "l"(b)); return d;
}
__device__ __forceinline__ float sqrt_ap(float x) {
    float r; asm("sqrt.approx.f32 %0, %1;" : "=f"(r) : "f"(x)); return r;
}
__device__ __forceinline__ float ex2_ap(float x) {
    float r; asm("ex2.approx.f32 %0, %1;" : "=f"(r) : "f"(x)); return r;
}
__device__ __forceinline__ float lg2_ap(float x) {
    float r; asm("lg2.approx.f32 %0, %1;" : "=f"(r) : "f"(x)); return r;
}

__global__ void __launch_bounds__(256, 5) smoothed_fused(
    const float* __restrict__ p,
    const float* __restrict__ centers,
    const float* __restrict__ radii,
    const float* __restrict__ tfs,
    float* __restrict__ out, int npts) {

    __shared__ __align__(16) float  shc[N_SPH * 28];   // 14336 B general consts
    __shared__ __align__(16) float  shc2[N_SPH * 8];   //  4096 B identity consts
    __shared__ __align__(16) float4 sbuf[CAP];         //  4096 B compacted points
    __shared__ float  spart[4 * 257];                  //  4112 B group partials
    __shared__ float  s_red[8];                        //  warp partials (4 sum, 4 sig)
    __shared__ float  s_R2;
    __shared__ int    s_count;
    __shared__ int    s_ident;

    const int tid = threadIdx.x;
    if (tid == 0) { s_count = 0; s_ident = 1; }

    // ---- prefetch this thread's 4 points ----
    int t = blockIdx.x * 256 + tid;
    int base = t * 4;
    float4 va, vb, vc;
    bool inb = base < npts;
    if (inb) {
        const float4* p4 = reinterpret_cast<const float4*>(p);
        int f = t * 3;
        va = p4[f]; vb = p4[f + 1]; vc = p4[f + 2];
    }
    __syncthreads();   // s_count / s_ident init visible

    // ---- phase A: threads 0..127 build consts + LSE threshold terms ----
    float my_sum = 0.0f, my_sig = 1e30f;
    if (tid < N_SPH) {
        int i = tid;
        float T[3][3];
        bool identl = true;
        #pragma unroll
        for (int r = 0; r < 3; ++r)
            #pragma unroll
            for (int c = 0; c < 3; ++c) {
                float tv = tfs[i * 9 + r * 3 + c];
                if (tv != 0.0f) identl = false;
                T[r][c] = tv + ((r == c) ? 1.0f : 0.0f);
            }
        if (!identl) atomicAnd(&s_ident, 0);

        float cx = centers[i * 3], cy = centers[i * 3 + 1], cz = centers[i * 3 + 2];
        float rad = radii[i];
        float b = 46.16624130844683f * rad;  // 32*log2(e)*r

        float* s = shc + i * 28;
        #pragma unroll
        for (int r = 0; r < 3; ++r) {
            float cs3[4] = {T[r][0], T[r][1], T[r][2],
                            (r == 0 ? -cx : (r == 1 ? -cy : -cz))};
            #pragma unroll
            for (int c = 0; c < 4; ++c) {
                s[(r * 4 + c) * 2]     = cs3[c];
                s[(r * 4 + c) * 2 + 1] = cs3[c];
            }
        }
        s[24] = b; s[25] = b; s[26] = 0.f; s[27] = 0.f;

        float* s2 = shc2 + i * 8;
        s2[0] = -cx; s2[1] = -cx;
        s2[2] = -cy; s2[3] = -cy;
        s2[4] = -cz; s2[5] = -cz;
        s2[6] = b;   s2[7] = b;

        // sigma_min lower bound: lambda_min(T^T T) >= q - 2*sqrt(p2/6)
        float M00 = 0, M11 = 0, M22 = 0, M01 = 0, M02 = 0, M12 = 0;
        #pragma unroll
        for (int k = 0; k < 3; ++k) {
            float t0 = T[k][0], t1 = T[k][1], t2 = T[k][2];
            M00 = fmaf(t0, t0, M00); M11 = fmaf(t1, t1, M11); M22 = fmaf(t2, t2, M22);
            M01 = fmaf(t0, t1, M01); M02 = fmaf(t0, t2, M02); M12 = fmaf(t1, t2, M12);
        }
        float q  = (M00 + M11 + M22) * (1.0f / 3.0f);
        float a0 = M00 - q, a1 = M11 - q, a2 = M22 - q;
        float p2 = a0 * a0 + a1 * a1 + a2 * a2
                 + 2.0f * (M01 * M01 + M02 * M02 + M12 * M12);
        float lmin = q - 2.001f * sqrtf(fmaxf(p2, 0.0f) * (1.0f / 6.0f)) - 1e-6f;
        my_sig = sqrtf(fmaxf(lmin, 0.0f)) * 0.999f;   // one-sided lower bound

        // LSE term: a_i = ||c_i|| + r_i (upper bound, inflated)
        float cn = sqrtf(cx * cx + cy * cy + cz * cz) * 1.0002f + 1e-7f;
        my_sum = expf(32.0f * (cn + rad));   // inf on overflow -> no culling (safe)
    }
    // warp butterfly reduce (deterministic), 4 warps carry data
    #pragma unroll
    for (int d = 16; d; d >>= 1) {
        my_sum += __shfl_xor_sync(0xffffffffu, my_sum, d);
        my_sig  = fminf(my_sig, __shfl_xor_sync(0xffffffffu, my_sig, d));
    }
    if ((tid & 31) == 0 && tid < N_SPH) {
        s_red[tid >> 5]     = my_sum;
        s_red[(tid >> 5) + 4] = my_sig;
    }
    __syncthreads();
    if (tid == 0) {
        float S    = ((s_red[0] + s_red[1]) + (s_red[2] + s_red[3])) * 1.01f;
        float sigg = fminf(fminf(s_red[4], s_red[5]), fminf(s_red[6], s_red[7]));
        float thr2 = 1e30f;                          // default: no culling
        if (sigg > 1e-6f && !(S != S)) {             // S NaN-guard
            float Rnum = logf(S) + 13.8155106f + 0.03f;   // ln S + ln 1e6 + delta
            if (Rnum <= 0.0f) {
                thr2 = 0.0f;                         // everything clamps: cull all
            } else if (Rnum < 1e15f) {               // excludes inf (S overflow)
                float R = Rnum / (32.0f * sigg);
                thr2 = R * R * 1.002f;
            }
        }
        s_R2 = thr2;
    }
    __syncthreads();
    float R2 = s_R2;
    int ident = s_ident;

    // ---- phase B: classify, compact into shared (cap CAP), overflow slow path ----
    float x[4], y[4], z[4];
    bool nearf[4] = {false, false, false, false};
    int cnt = 0;
    if (inb) {
        x[0] = va.x; y[0] = va.y; z[0] = va.z;
        x[1] = va.w; y[1] = vb.x; z[1] = vb.y;
        x[2] = vb.z; y[2] = vb.w; z[2] = vc.x;
        x[3] = vc.y; y[3] = vc.z; z[3] = vc.w;
        #pragma unroll
        for (int k = 0; k < 4; ++k) {
            float n2 = fmaf(x[k], x[k], fmaf(y[k], y[k], z[k] * z[k]));
            nearf[k] = n2 < R2;
            if (!nearf[k]) out[base + k] = FASTVAL;
            cnt += nearf[k] ? 1 : 0;
        }
    }
    unsigned mask = 0xffffffffu;
    int lane = tid & 31;
    int incl = cnt;
    #pragma unroll
    for (int d = 1; d < 32; d <<= 1) {
        int v = __shfl_up_sync(mask, incl, d);
        if (lane >= d) incl += v;
    }
    int total = __shfl_sync(mask, incl, 31);
    int wbase = 0;
    if (lane == 0) wbase = (total > 0) ? atomicAdd(&s_count, total) : 0;
    wbase = __shfl_sync(mask, wbase, 0);
    int off = wbase + incl - cnt;
    #pragma unroll
    for (int k = 0; k < 4; ++k) {
        if (nearf[k]) {
            if (off < CAP) {
                sbuf[off] = make_float4(x[k], y[k], z[k], __int_as_float(base + k));
            } else {
                // overflow slow path: full scalar loop (correct, rare)
                float ssum = 0.f;
                for (int i = 0; i < N_SPH; ++i) {
                    const float* s = shc + i * 28;
                    float qx = fmaf(s[0], x[k], fmaf(s[2],  y[k], fmaf(s[4],  z[k], s[6])));
                    float qy = fmaf(s[8], x[k], fmaf(s[10], y[k], fmaf(s[12], z[k], s[14])));
                    float qz = fmaf(s[16], x[k], fmaf(s[18], y[k], fmaf(s[20], z[k], s[22])));
                    float d2 = fmaf(qx, qx, fmaf(qy, qy, qz * qz));
                    ssum += ex2_ap(fmaf(sqrt_ap(d2), -46.16624130844683f, s[24]));
                }
                out[base + k] = lg2_ap(fmaxf(ssum, 1e-6f)) * -0.021660849392498290f;
            }
            off++;
        }
    }
    __syncthreads();

    // ---- phase C: unit = (pair j, group g of 32 spheres); single pass typical ----
    // WARP-UNIFORM g: j = (u>>7)*32 + (u&31), g = (u>>5)&3
    int count = min(s_count, CAP);
    int pairs = (count + 1) >> 1;
    int total_u = ((pairs + 31) >> 5) << 7;   // pairs rounded to 32, x4 groups

    for (int u = tid; u < total_u; u += 256) {
        int j = ((u >> 7) << 5) | (u & 31);
        int g = (u >> 5) & 3;
        if (j >= pairs) continue;

        int ia = 2 * j;
        int ib = min(2 * j + 1, count - 1);
        float4 A = sbuf[ia];
        float4 B = sbuf[ib];

        u64 X = pk2(A.x, B.x), Y = pk2(A.y, B.y), Z = pk2(A.z, B.z);
        float s0 = 0.f, s1 = 0.f;

        if (ident) {
            // identity T: q = p - c  (bit-identical to the general path when T=I)
            const float* cb2 = shc2 + g * (32 * 8);
            #pragma unroll 4
            for (int sp = 0; sp < 32; ++sp) {
                const ulonglong2* C = reinterpret_cast<const ulonglong2*>(cb2 + sp * 8);
                ulonglong2 n0 = C[0];  // (ncx, ncy)
                ulonglong2 n1 = C[1];  // (ncz, b)

                u64 qx = f2add(X, n0.x);
                u64 qy = f2add(Y, n0.y);
                u64 qz = f2add(Z, n1.x);
                u64 d2 = f2fma(qx, qx, f2fma(qy, qy, f2mul(qz, qz)));

                float2 d  = up2(d2);
                float2 bs = up2(n1.y);
                s0 += ex2_ap(fmaf(sqrt_ap(d.x), -46.16624130844683f, bs.x));
                s1 += ex2_ap(fmaf(sqrt_ap(d.y), -46.16624130844683f, bs.y));
            }
        } else {
            const float* cb = shc + g * (32 * 28);
            #pragma unroll 4
            for (int sp = 0; sp < 32; ++sp) {
                const ulonglong2* C = reinterpret_cast<const ulonglong2*>(cb + sp * 28);
                ulonglong2 m0 = C[0], m1 = C[1], m2 = C[2];
                ulonglong2 m3 = C[3], m4 = C[4], m5 = C[5];
                u64 bb = reinterpret_cast<const u64*>(C)[12];

                u64 qx = f2fma(m0.x, X, f2fma(m0.y, Y, f2fma(m1.x, Z, m1.y)));
                u64 qy = f2fma(m2.x, X, f2fma(m2.y, Y, f2fma(m3.x, Z, m3.y)));
                u64 qz = f2fma(m4.x, X, f2fma(m4.y, Y, f2fma(m5.x, Z, m5.y)));
                u64 d2 = f2fma(qx, qx, f2fma(qy, qy, f2mul(qz, qz)));

                float2 d  = up2(d2);
                float2 bs = up2(bb);
                s0 += ex2_ap(fmaf(sqrt_ap(d.x), -46.16624130844683f, bs.x));
                s1 += ex2_ap(fmaf(sqrt_ap(d.y), -46.16624130844683f, bs.y));
            }
        }

        spart[g * 257 + ia] = s0;
        if (2 * j + 1 < count) spart[g * 257 + ib] = s1;
    }
    __syncthreads();

    // ---- phase D: fixed-order combine of 4 group partials per point ----
    const float NEG_LN2_32 = -0.021660849392498290f;
    for (int pt = tid; pt < count; pt += 256) {
        float a0 = spart[pt];
        float a1 = spart[257 + pt];
        float a2 = spart[2 * 257 + pt];
        float a3 = spart[3 * 257 + pt];
        float s = (a0 + a1) + (a2 + a3);
        out[__float_as_int(sbuf[pt].w)] = lg2_ap(fmaxf(s, 1e-6f)) * NEG_LN2_32;
    }
}

extern "C" void kernel_launch(void* const* d_in, const int* in_sizes, int n_in,
                              void* d_out, int out_size) {
    const float* p       = (const float*)d_in[0];
    const float* centers = (const float*)d_in[1];
    const float* radii   = (const float*)d_in[2];
    const float* tfs     = (const float*)d_in[3];
    float* out = (float*)d_out;

    int npts = in_sizes[0] / 3;
    int blocks = (npts + 1023) / 1024;  // 256 threads x 4 points
    smoothed_fused<<<blocks, 256>>>(p, centers, radii, tfs, out, npts);
}